// round 9
// baseline (speedup 1.0000x reference)
#include <cuda_runtime.h>
#include <cuda_bf16.h>
#include <cstdint>

// ============================================================================
// Compile-time reproduction of np.random.RandomState(0) op sequence
// ============================================================================
struct OpT { int kind; int a; int b; };   // kind: 0=rx 1=ry 2=rz 3=cnot
struct MTc { unsigned mt[624]; int mti; };

constexpr unsigned mt_next(MTc &s) {
    if (s.mti >= 624) {
        for (int i = 0; i < 624; ++i) {
            unsigned y = (s.mt[i] & 0x80000000u) | (s.mt[(i + 1) % 624] & 0x7fffffffu);
            unsigned v = s.mt[(i + 397) % 624] ^ (y >> 1);
            if (y & 1u) v ^= 0x9908b0dfu;
            s.mt[i] = v;
        }
        s.mti = 0;
    }
    unsigned y = s.mt[s.mti++];
    y ^= y >> 11;
    y ^= (y << 7)  & 0x9d2c5680u;
    y ^= (y << 15) & 0xefc60000u;
    y ^= y >> 18;
    return y;
}
constexpr unsigned mt_interval(MTc &s, unsigned maxv) {
    unsigned mask = maxv;
    mask |= mask >> 1; mask |= mask >> 2; mask |= mask >> 4;
    mask |= mask >> 8; mask |= mask >> 16;
    unsigned v = mt_next(s) & mask;
    while (v > maxv) v = mt_next(s) & mask;
    return v;
}
struct Ops { OpT ops[20]; };
constexpr Ops make_ops() {
    Ops o{};
    MTc s{};
    s.mt[0] = 0u;
    for (int i = 1; i < 624; ++i)
        s.mt[i] = 1812433253u * (s.mt[i - 1] ^ (s.mt[i - 1] >> 30)) + (unsigned)i;
    s.mti = 624;
    for (int i = 0; i < 20; ++i) {
        unsigned k = mt_interval(s, 3u);
        if (k == 3u) {
            int perm[8] = {0,1,2,3,4,5,6,7};
            for (int j = 7; j >= 1; --j) {
                unsigned x = mt_interval(s, (unsigned)j);
                int t = perm[j]; perm[j] = perm[x]; perm[x] = t;
            }
            o.ops[i] = OpT{3, perm[0], perm[1]};
        } else {
            unsigned w = mt_interval(s, 7u);
            o.ops[i] = OpT{(int)k, (int)w, 0};
        }
    }
    return o;
}
constexpr Ops OPS = make_ops();

// ============================================================================
// Device globals: circuit matrix U (real/imag), built once by kernel A.
// U[j][i] = <j| U |i> ; layout row-major [j][i], 256x256 floats each.
// ============================================================================
__device__ float g_Ur[256 * 256];
__device__ float g_Ui[256 * 256];

// ============================================================================
// Packed fp32x2 helpers (verified R5 versions)
// ============================================================================
__device__ __forceinline__ float2 f2mul(float2 a, float2 b) {
    float2 d;
    asm("{\n\t"
        ".reg .b64 ra, rb, rd;\n\t"
        "mov.b64 ra, {%2, %3};\n\t"
        "mov.b64 rb, {%4, %5};\n\t"
        "mul.rn.f32x2 rd, ra, rb;\n\t"
        "mov.b64 {%0, %1}, rd;\n\t"
        "}"
        : "=f"(d.x), "=f"(d.y)
        : "f"(a.x), "f"(a.y), "f"(b.x), "f"(b.y));
    return d;
}
__device__ __forceinline__ float2 f2fma(float2 a, float2 b, float2 c) {
    float2 d;
    asm("{\n\t"
        ".reg .b64 ra, rb, rc, rd;\n\t"
        "mov.b64 ra, {%2, %3};\n\t"
        "mov.b64 rb, {%4, %5};\n\t"
        "mov.b64 rc, {%6, %7};\n\t"
        "fma.rn.f32x2 rd, ra, rb, rc;\n\t"
        "mov.b64 {%0, %1}, rd;\n\t"
        "}"
        : "=f"(d.x), "=f"(d.y)
        : "f"(a.x), "f"(a.y), "f"(b.x), "f"(b.y), "f"(c.x), "f"(c.y));
    return d;
}
__device__ __forceinline__ float2 shfl_xor2(float2 v, int m) {
    v.x = __shfl_xor_sync(0xffffffffu, v.x, m);
    v.y = __shfl_xor_sync(0xffffffffu, v.y, m);
    return v;
}

// ============================================================================
// Gate application — VERIFIED R5 version (amp j = lane*8 + r; pack k=r>>1,
// half=r&1 (.x even); wire w <-> bit p = 7-w; p<3 reg bits, p>=3 lane bits).
// ============================================================================
template<int KIND, int A, int B>
__device__ __forceinline__ void gateP(float2 (&RE)[4], float2 (&IM)[4], int lane,
                                      float cc, float ss) {
    constexpr unsigned FULL = 0xffffffffu;
    if constexpr (KIND == 3) {                       // CNOT ctrl A tgt B
        constexpr int pc = 7 - A, pt = 7 - B;
        if constexpr (pc < 3 && pt < 3) {
            if constexpr (pt == 0) {
                constexpr int cb = pc - 1;
                #pragma unroll
                for (int k = 0; k < 4; ++k)
                    if ((k >> cb) & 1) {
                        RE[k] = make_float2(RE[k].y, RE[k].x);
                        IM[k] = make_float2(IM[k].y, IM[k].x);
                    }
            } else if constexpr (pc == 0) {
                constexpr int tb = pt - 1, mm = 1 << tb;
                #pragma unroll
                for (int k = 0; k < 4; ++k)
                    if (!((k >> tb) & 1)) {
                        int q = k + mm;
                        float t = RE[k].y; RE[k].y = RE[q].y; RE[q].y = t;
                        t = IM[k].y; IM[k].y = IM[q].y; IM[q].y = t;
                    }
            } else {
                constexpr int cb = pc - 1, tb = pt - 1, mm = 1 << tb;
                #pragma unroll
                for (int k = 0; k < 4; ++k)
                    if (((k >> cb) & 1) && !((k >> tb) & 1)) {
                        float2 t = RE[k]; RE[k] = RE[k + mm]; RE[k + mm] = t;
                        t = IM[k]; IM[k] = IM[k + mm]; IM[k + mm] = t;
                    }
            }
        } else if constexpr (pc < 3 && pt >= 3) {
            constexpr int ml = 1 << (pt - 3);
            if constexpr (pc == 0) {
                #pragma unroll
                for (int k = 0; k < 4; ++k) {
                    RE[k].y = __shfl_xor_sync(FULL, RE[k].y, ml);
                    IM[k].y = __shfl_xor_sync(FULL, IM[k].y, ml);
                }
            } else {
                constexpr int cb = pc - 1;
                #pragma unroll
                for (int k = 0; k < 4; ++k)
                    if ((k >> cb) & 1) {
                        RE[k] = shfl_xor2(RE[k], ml);
                        IM[k] = shfl_xor2(IM[k], ml);
                    }
            }
        } else if constexpr (pc >= 3 && pt < 3) {
            bool bc = (lane >> (pc - 3)) & 1;
            if constexpr (pt == 0) {
                #pragma unroll
                for (int k = 0; k < 4; ++k) {
                    float2 v = RE[k];
                    RE[k] = bc ? make_float2(v.y, v.x) : v;
                    float2 u = IM[k];
                    IM[k] = bc ? make_float2(u.y, u.x) : u;
                }
            } else {
                constexpr int tb = pt - 1, mm = 1 << tb;
                #pragma unroll
                for (int k = 0; k < 4; ++k)
                    if (!((k >> tb) & 1)) {
                        int q = k + mm;
                        float2 a = RE[k], b2v = RE[q];
                        RE[k] = bc ? b2v : a; RE[q] = bc ? a : b2v;
                        float2 c2 = IM[k], d2 = IM[q];
                        IM[k] = bc ? d2 : c2; IM[q] = bc ? c2 : d2;
                    }
            }
        } else {
            int bc = (lane >> (pc - 3)) & 1;
            int src = lane ^ (bc << (pt - 3));
            #pragma unroll
            for (int k = 0; k < 4; ++k) {
                RE[k].x = __shfl_sync(FULL, RE[k].x, src);
                RE[k].y = __shfl_sync(FULL, RE[k].y, src);
                IM[k].x = __shfl_sync(FULL, IM[k].x, src);
                IM[k].y = __shfl_sync(FULL, IM[k].y, src);
            }
        }
    } else if constexpr (KIND == 2) {                // RZ
        constexpr int p = 7 - A;
        float2 C = make_float2(cc, cc);
        if constexpr (p == 0) {
            float2 SE  = make_float2(-ss,  ss);
            float2 NSE = make_float2( ss, -ss);
            #pragma unroll
            for (int k = 0; k < 4; ++k) {
                float2 r0 = f2fma(NSE, IM[k], f2mul(C, RE[k]));
                IM[k] = f2fma(SE, RE[k], f2mul(C, IM[k]));
                RE[k] = r0;
            }
        } else if constexpr (p < 3) {
            constexpr int kb = p - 1;
            float2 SP = make_float2( ss,  ss);
            float2 SN = make_float2(-ss, -ss);
            #pragma unroll
            for (int k = 0; k < 4; ++k) {
                float2 SE  = ((k >> kb) & 1) ? SP : SN;
                float2 NSE = ((k >> kb) & 1) ? SN : SP;
                float2 r0 = f2fma(NSE, IM[k], f2mul(C, RE[k]));
                IM[k] = f2fma(SE, RE[k], f2mul(C, IM[k]));
                RE[k] = r0;
            }
        } else {
            float se = ((lane >> (p - 3)) & 1) ? ss : -ss;
            float2 SE  = make_float2( se,  se);
            float2 NSE = make_float2(-se, -se);
            #pragma unroll
            for (int k = 0; k < 4; ++k) {
                float2 r0 = f2fma(NSE, IM[k], f2mul(C, RE[k]));
                IM[k] = f2fma(SE, RE[k], f2mul(C, IM[k]));
                RE[k] = r0;
            }
        }
    } else if constexpr (KIND == 0) {                // RX
        constexpr int p = 7 - A;
        float2 C  = make_float2(cc, cc);
        float2 S  = make_float2( ss,  ss);
        float2 NS = make_float2(-ss, -ss);
        if constexpr (p == 0) {
            #pragma unroll
            for (int k = 0; k < 4; ++k) {
                float2 isw = make_float2(IM[k].y, IM[k].x);
                float2 rsw = make_float2(RE[k].y, RE[k].x);
                RE[k] = f2fma(S,  isw, f2mul(C, RE[k]));
                IM[k] = f2fma(NS, rsw, f2mul(C, IM[k]));
            }
        } else if constexpr (p < 3) {
            constexpr int kb = p - 1, mm = 1 << kb;
            #pragma unroll
            for (int k = 0; k < 4; ++k)
                if (!((k >> kb) & 1)) {
                    int q = k + mm;
                    float2 rk = RE[k], ik = IM[k], rq = RE[q], iq = IM[q];
                    RE[k] = f2fma(S,  iq, f2mul(C, rk));
                    IM[k] = f2fma(NS, rq, f2mul(C, ik));
                    RE[q] = f2fma(S,  ik, f2mul(C, rq));
                    IM[q] = f2fma(NS, rk, f2mul(C, iq));
                }
        } else {
            constexpr int m = 1 << (p - 3);
            #pragma unroll
            for (int k = 0; k < 4; ++k) {
                float2 pr = shfl_xor2(RE[k], m);
                float2 pi = shfl_xor2(IM[k], m);
                RE[k] = f2fma(S,  pi, f2mul(C, RE[k]));
                IM[k] = f2fma(NS, pr, f2mul(C, IM[k]));
            }
        }
    } else {                                         // RY
        constexpr int p = 7 - A;
        float2 C = make_float2(cc, cc);
        if constexpr (p == 0) {
            float2 MS = make_float2(-ss, ss);
            #pragma unroll
            for (int k = 0; k < 4; ++k) {
                float2 rsw = make_float2(RE[k].y, RE[k].x);
                float2 isw = make_float2(IM[k].y, IM[k].x);
                RE[k] = f2fma(MS, rsw, f2mul(C, RE[k]));
                IM[k] = f2fma(MS, isw, f2mul(C, IM[k]));
            }
        } else if constexpr (p < 3) {
            constexpr int kb = p - 1, mm = 1 << kb;
            float2 S  = make_float2( ss,  ss);
            float2 NS = make_float2(-ss, -ss);
            #pragma unroll
            for (int k = 0; k < 4; ++k)
                if (!((k >> kb) & 1)) {
                    int q = k + mm;
                    float2 rk = RE[k], rq = RE[q];
                    RE[k] = f2fma(NS, rq, f2mul(C, rk));
                    RE[q] = f2fma(S,  rk, f2mul(C, rq));
                    float2 ik = IM[k], iq = IM[q];
                    IM[k] = f2fma(NS, iq, f2mul(C, ik));
                    IM[q] = f2fma(S,  ik, f2mul(C, iq));
                }
        } else {
            constexpr int m = 1 << (p - 3);
            float sg = ((lane >> (p - 3)) & 1) ? ss : -ss;
            float2 SG = make_float2(sg, sg);
            #pragma unroll
            for (int k = 0; k < 4; ++k) {
                float2 pr = shfl_xor2(RE[k], m);
                float2 pi = shfl_xor2(IM[k], m);
                RE[k] = f2fma(SG, pr, f2mul(C, RE[k]));
                IM[k] = f2fma(SG, pi, f2mul(C, IM[k]));
            }
        }
    }
}

template<int I>
__device__ __forceinline__ void apply_opP(float2 (&RE)[4], float2 (&IM)[4], int lane,
                                          const float* cs) {
    gateP<OPS.ops[I].kind, OPS.ops[I].a, OPS.ops[I].b>(RE, IM, lane, cs[2 * I], cs[2 * I + 1]);
}

// ============================================================================
// Kernel A: build U by simulating the 256 basis states (warp per basis state).
// Grid 32 x 256 threads; warp (blockIdx*8 + wid) handles basis state i.
// ============================================================================
__global__ __launch_bounds__(256)
void build_u_kernel(const float* __restrict__ rp, const float* __restrict__ ryt) {
    __shared__ float cs[56];
    {
        int t = threadIdx.x;
        if (t < 20) {
            float sv, cv; sincosf(__ldg(rp + t) * 0.5f, &sv, &cv);
            cs[2 * t] = cv; cs[2 * t + 1] = sv;
        } else if (t < 28) {
            int w = t - 20;
            float sv, cv; sincosf(__ldg(ryt + w) * 0.5f, &sv, &cv);
            cs[40 + 2 * w] = cv; cs[41 + 2 * w] = sv;
        }
    }
    __syncthreads();

    int lane = threadIdx.x & 31;
    int i = blockIdx.x * 8 + (threadIdx.x >> 5);     // basis state 0..255

    float2 RE[4], IM[4];
    int li = i >> 3, ki = (i & 7) >> 1, hi = i & 1;
    #pragma unroll
    for (int k = 0; k < 4; ++k) {
        RE[k] = make_float2(0.0f, 0.0f);
        IM[k] = make_float2(0.0f, 0.0f);
    }
    if (lane == li) {
        if (hi == 0) RE[ki].x = 1.0f; else RE[ki].y = 1.0f;
    }

    apply_opP<0>(RE, IM, lane, cs);   apply_opP<1>(RE, IM, lane, cs);
    apply_opP<2>(RE, IM, lane, cs);   apply_opP<3>(RE, IM, lane, cs);
    apply_opP<4>(RE, IM, lane, cs);   apply_opP<5>(RE, IM, lane, cs);
    apply_opP<6>(RE, IM, lane, cs);   apply_opP<7>(RE, IM, lane, cs);
    apply_opP<8>(RE, IM, lane, cs);   apply_opP<9>(RE, IM, lane, cs);
    apply_opP<10>(RE, IM, lane, cs);  apply_opP<11>(RE, IM, lane, cs);
    apply_opP<12>(RE, IM, lane, cs);  apply_opP<13>(RE, IM, lane, cs);
    apply_opP<14>(RE, IM, lane, cs);  apply_opP<15>(RE, IM, lane, cs);
    apply_opP<16>(RE, IM, lane, cs);  apply_opP<17>(RE, IM, lane, cs);
    apply_opP<18>(RE, IM, lane, cs);  apply_opP<19>(RE, IM, lane, cs);

    gateP<1, 0, 0>(RE, IM, lane, cs[40], cs[41]);
    gateP<1, 1, 0>(RE, IM, lane, cs[42], cs[43]);
    gateP<1, 2, 0>(RE, IM, lane, cs[44], cs[45]);
    gateP<1, 3, 0>(RE, IM, lane, cs[46], cs[47]);
    gateP<1, 4, 0>(RE, IM, lane, cs[48], cs[49]);
    gateP<1, 5, 0>(RE, IM, lane, cs[50], cs[51]);
    gateP<1, 6, 0>(RE, IM, lane, cs[52], cs[53]);
    gateP<1, 7, 0>(RE, IM, lane, cs[54], cs[55]);

    // warp holds column U[:, i]: amp j = lane*8 + 2k (+1). Store U[j][i].
    #pragma unroll
    for (int k = 0; k < 4; ++k) {
        int j0 = lane * 8 + 2 * k;
        g_Ur[(size_t)j0 * 256 + i]       = RE[k].x;
        g_Ur[(size_t)(j0 + 1) * 256 + i] = RE[k].y;
        g_Ui[(size_t)j0 * 256 + i]       = IM[k].x;
        g_Ui[(size_t)(j0 + 1) * 256 + i] = IM[k].y;
    }
}

// ============================================================================
// Kernel B: fused  S0-build -> GEMM1 (F,G = S0 @ Ur^T, Ui^T) -> probs/expv
//           -> W1 relu -> GEMM2 (out = H @ W2^T + b2)
// 64 rows/block, 256 threads (8 warps), grid 256.
// ============================================================================
#define AST 132   // As0 row stride in uint2 (128 data + pad; 132 % 16 == 4)
#define BST 36    // slice/B row stride in uint2 (proven conflict-free)

__device__ __forceinline__ uint32_t f2tf32(float f) {
    uint32_t r;
    asm("cvt.rna.tf32.f32 %0, %1;" : "=r"(r) : "f"(f));
    return r;
}

__global__ __launch_bounds__(256)
void qff_kernel(const float* __restrict__ x, const float* __restrict__ W1,
                const float* __restrict__ b1,
                const float* __restrict__ W2, const float* __restrict__ b2,
                float* __restrict__ out) {
    extern __shared__ char smraw[];
    uint2* As0 = (uint2*)smraw;                 // [64][AST]   S0 tile (tf32 frags)
    uint2* Bsl = As0 + 64 * AST;                // 4608 uint2: GEMM1 Br+Bi / GEMM2 W2
    float* evb = (float*)(Bsl + 4608);          // [4][64][8]
    float* evf = evb + 4 * 64 * 8;              // [64][8]

    int t = threadIdx.x;
    int lane = t & 31, wid = t >> 5;
    int g = lane >> 2, tg = lane & 3;
    int bm = blockIdx.x * 64;

    // ---------------- Phase 1: build S0 tile (tf32 fragment layout) ----------
    {
        int row = t >> 2, q = t & 3;            // 4 threads per row, 64 amps each
        const float* xr = x + (size_t)(bm + row) * 512;
        float c[8], s[8];
        #pragma unroll
        for (int w = 0; w < 8; ++w) {
            float v = __ldg(xr + w) * 0.5f;
            __sincosf(v, &s[w], &c[w]);
        }
        // amp j = q*64 + m ; bit p of j <-> wire 7-p
        float fq = ((q & 2) ? s[0] : c[0]) * ((q & 1) ? s[1] : c[1]);
        float FP[4], Q4[4], R4[4], QR[16];
        #pragma unroll
        for (int idx = 0; idx < 4; ++idx) {
            FP[idx] = fq * ((idx & 2) ? s[2] : c[2]) * ((idx & 1) ? s[3] : c[3]);
            Q4[idx] = ((idx & 2) ? s[4] : c[4]) * ((idx & 1) ? s[5] : c[5]);
            R4[idx] = ((idx & 2) ? s[6] : c[6]) * ((idx & 1) ? s[7] : c[7]);
        }
        #pragma unroll
        for (int x16 = 0; x16 < 16; ++x16)
            QR[x16] = Q4[x16 >> 2] * R4[x16 & 3];
        #pragma unroll
        for (int mc = 0; mc < 8; ++mc) {
            float v[8];
            #pragma unroll
            for (int u = 0; u < 8; ++u) {
                int m = mc * 8 + u;
                v[u] = FP[m >> 4] * QR[m & 15];
            }
            int cb = (q * 8 + mc) * 4;
            #pragma unroll
            for (int u = 0; u < 4; ++u)
                As0[row * AST + cb + u] = make_uint2(f2tf32(v[u]), f2tf32(v[u + 4]));
        }
    }
    __syncthreads();

    // ---------------- Phase 2: GEMM1 + probs + bit-marginal accumulation -----
    int wm = (wid >> 2) * 32;        // 2 M-warps over 64 rows
    int wn16 = (wid & 3) * 16;       // 4 N-warps over 64-j chunk
    // per-thread, per 4 rows: total-prob + 4 signed bit sums
    float ptotA[4] = {0, 0, 0, 0};
    float D0A[4] = {0, 0, 0, 0};     // bit0 (w7)
    float D3A[4] = {0, 0, 0, 0};     // bit3 (w4)
    float D6A[4] = {0, 0, 0, 0};     // bit6 (w1)
    float D7A[4] = {0, 0, 0, 0};     // bit7 (w0)
    uint2* Br = Bsl;
    uint2* Bi = Bsl + 64 * BST;

    for (int jc = 0; jc < 4; ++jc) {             // 4 j-chunks of 64 columns
        float accF[2][2][4], accG[2][2][4];
        #pragma unroll
        for (int f = 0; f < 2; ++f)
            #pragma unroll
            for (int n = 0; n < 2; ++n)
                #pragma unroll
                for (int qd = 0; qd < 4; ++qd) { accF[f][n][qd] = 0.0f; accG[f][n][qd] = 0.0f; }

        for (int ks = 0; ks < 4; ++ks) {         // K slices of 64
            __syncthreads();
            {   // stage Br/Bi [64 j][64 k] in fragment layout
                int j = t >> 2, kg = t & 3;
                size_t base = (size_t)(jc * 64 + j) * 256 + ks * 64 + kg * 16;
                const float4* pr = (const float4*)(g_Ur + base);
                const float4* pi = (const float4*)(g_Ui + base);
                float4 r0 = pr[0], r1 = pr[1], r2 = pr[2], r3 = pr[3];
                float4 i0 = pi[0], i1 = pi[1], i2 = pi[2], i3 = pi[3];
                uint2* br = Br + j * BST + (kg * 2) * 4;
                uint2* bi = Bi + j * BST + (kg * 2) * 4;
                br[0] = make_uint2(f2tf32(r0.x), f2tf32(r1.x));
                br[1] = make_uint2(f2tf32(r0.y), f2tf32(r1.y));
                br[2] = make_uint2(f2tf32(r0.z), f2tf32(r1.z));
                br[3] = make_uint2(f2tf32(r0.w), f2tf32(r1.w));
                br[4] = make_uint2(f2tf32(r2.x), f2tf32(r3.x));
                br[5] = make_uint2(f2tf32(r2.y), f2tf32(r3.y));
                br[6] = make_uint2(f2tf32(r2.z), f2tf32(r3.z));
                br[7] = make_uint2(f2tf32(r2.w), f2tf32(r3.w));
                bi[0] = make_uint2(f2tf32(i0.x), f2tf32(i1.x));
                bi[1] = make_uint2(f2tf32(i0.y), f2tf32(i1.y));
                bi[2] = make_uint2(f2tf32(i0.z), f2tf32(i1.z));
                bi[3] = make_uint2(f2tf32(i0.w), f2tf32(i1.w));
                bi[4] = make_uint2(f2tf32(i2.x), f2tf32(i3.x));
                bi[5] = make_uint2(f2tf32(i2.y), f2tf32(i3.y));
                bi[6] = make_uint2(f2tf32(i2.z), f2tf32(i3.z));
                bi[7] = make_uint2(f2tf32(i2.w), f2tf32(i3.w));
            }
            __syncthreads();

            #pragma unroll
            for (int kk = 0; kk < 8; ++kk) {
                int pos = (ks * 8 + kk) * 4 + tg;
                uint2 a0 = As0[(wm + g) * AST + pos];
                uint2 a1 = As0[(wm + g + 8) * AST + pos];
                uint2 a2 = As0[(wm + g + 16) * AST + pos];
                uint2 a3 = As0[(wm + g + 24) * AST + pos];
                uint32_t af[2][4] = {
                    { a0.x, a1.x, a0.y, a1.y },
                    { a2.x, a3.x, a2.y, a3.y }
                };
                int bpos = kk * 4 + tg;
                uint2 br0 = Br[(wn16 + g) * BST + bpos];
                uint2 br1 = Br[(wn16 + 8 + g) * BST + bpos];
                uint2 bi0 = Bi[(wn16 + g) * BST + bpos];
                uint2 bi1 = Bi[(wn16 + 8 + g) * BST + bpos];

                #pragma unroll
                for (int f = 0; f < 2; ++f) {
                    asm volatile(
                        "mma.sync.aligned.m16n8k8.row.col.f32.tf32.tf32.f32 "
                        "{%0,%1,%2,%3}, {%4,%5,%6,%7}, {%8,%9}, {%0,%1,%2,%3};"
                        : "+f"(accF[f][0][0]), "+f"(accF[f][0][1]),
                          "+f"(accF[f][0][2]), "+f"(accF[f][0][3])
                        : "r"(af[f][0]), "r"(af[f][1]), "r"(af[f][2]), "r"(af[f][3]),
                          "r"(br0.x), "r"(br0.y));
                    asm volatile(
                        "mma.sync.aligned.m16n8k8.row.col.f32.tf32.tf32.f32 "
                        "{%0,%1,%2,%3}, {%4,%5,%6,%7}, {%8,%9}, {%0,%1,%2,%3};"
                        : "+f"(accF[f][1][0]), "+f"(accF[f][1][1]),
                          "+f"(accF[f][1][2]), "+f"(accF[f][1][3])
                        : "r"(af[f][0]), "r"(af[f][1]), "r"(af[f][2]), "r"(af[f][3]),
                          "r"(br1.x), "r"(br1.y));
                    asm volatile(
                        "mma.sync.aligned.m16n8k8.row.col.f32.tf32.tf32.f32 "
                        "{%0,%1,%2,%3}, {%4,%5,%6,%7}, {%8,%9}, {%0,%1,%2,%3};"
                        : "+f"(accG[f][0][0]), "+f"(accG[f][0][1]),
                          "+f"(accG[f][0][2]), "+f"(accG[f][0][3])
                        : "r"(af[f][0]), "r"(af[f][1]), "r"(af[f][2]), "r"(af[f][3]),
                          "r"(bi0.x), "r"(bi0.y));
                    asm volatile(
                        "mma.sync.aligned.m16n8k8.row.col.f32.tf32.tf32.f32 "
                        "{%0,%1,%2,%3}, {%4,%5,%6,%7}, {%8,%9}, {%0,%1,%2,%3};"
                        : "+f"(accG[f][1][0]), "+f"(accG[f][1][1]),
                          "+f"(accG[f][1][2]), "+f"(accG[f][1][3])
                        : "r"(af[f][0]), "r"(af[f][1]), "r"(af[f][2]), "r"(af[f][3]),
                          "r"(bi1.x), "r"(bi1.y));
                }
            }
        }

        // chunk epilogue: probs -> bit marginals. col j = jc*64 + wn16 + n*8 + tg*2 {+1}
        float sj6 = (jc & 1) ? -1.0f : 1.0f;     // bit6 of j
        float sj7 = (jc & 2) ? -1.0f : 1.0f;     // bit7 of j
        #pragma unroll
        for (int f = 0; f < 2; ++f) {
            #pragma unroll
            for (int half = 0; half < 2; ++half) {
                int rr = f * 2 + half;
                int o = half * 2;                // acc idx: c0,c1 (row g) / c2,c3 (row g+8)
                float s_n[2], d_n[2];
                #pragma unroll
                for (int n = 0; n < 2; ++n) {
                    float p0 = accF[f][n][o] * accF[f][n][o] + accG[f][n][o] * accG[f][n][o];
                    float p1 = accF[f][n][o+1] * accF[f][n][o+1] + accG[f][n][o+1] * accG[f][n][o+1];
                    s_n[n] = p0 + p1;
                    d_n[n] = p0 - p1;
                }
                float ssum = s_n[0] + s_n[1];
                ptotA[rr] += ssum;
                D0A[rr] += d_n[0] + d_n[1];
                D3A[rr] += s_n[0] - s_n[1];
                D6A[rr] += sj6 * ssum;
                D7A[rr] += sj7 * ssum;
            }
        }
    }

    // per-thread ev vectors (thread-fixed signs for bits 1,2,4,5)
    float sb1 = (tg & 1) ? -1.0f : 1.0f;     // bit1 -> w6
    float sb2 = (tg & 2) ? -1.0f : 1.0f;     // bit2 -> w5
    float sb4 = (wid & 1) ? -1.0f : 1.0f;    // bit4 -> w3
    float sb5 = (wid & 2) ? -1.0f : 1.0f;    // bit5 -> w2
    float evv[4][8];
    #pragma unroll
    for (int rr = 0; rr < 4; ++rr) {
        evv[rr][0] = D7A[rr];
        evv[rr][1] = D6A[rr];
        evv[rr][2] = sb5 * ptotA[rr];
        evv[rr][3] = sb4 * ptotA[rr];
        evv[rr][4] = D3A[rr];
        evv[rr][5] = sb2 * ptotA[rr];
        evv[rr][6] = sb1 * ptotA[rr];
        evv[rr][7] = D0A[rr];
    }
    // reduce over tg (lanes differing in low 2 bits)
    #pragma unroll
    for (int off = 1; off <= 2; off <<= 1)
        #pragma unroll
        for (int rr = 0; rr < 4; ++rr)
            #pragma unroll
            for (int w = 0; w < 8; ++w)
                evv[rr][w] += __shfl_xor_sync(0xffffffffu, evv[rr][w], off);

    if (tg == 0) {
        #pragma unroll
        for (int rr = 0; rr < 4; ++rr) {
            int row = wm + (rr >> 1) * 16 + (rr & 1) * 8 + g;
            #pragma unroll
            for (int w = 0; w < 8; ++w)
                evb[((wid & 3) * 64 + row) * 8 + w] = evv[rr][w];
        }
    }
    __syncthreads();

    // final ev: sum 4 N-warp partials
    #pragma unroll
    for (int task = 0; task < 2; ++task) {
        int id = task * 256 + t;
        evf[id] = evb[id] + evb[512 + id] + evb[1024 + id] + evb[1536 + id];
    }
    __syncthreads();

    // ---------------- Phase 3: W1 relu -> As2 fragments ----------------------
    uint2* As2 = As0;                            // reuse, stride BST
    {
        int row = t >> 2, q = t & 3;             // thread: 16 h outputs
        float ev[8];
        #pragma unroll
        for (int w = 0; w < 8; ++w) ev[w] = evf[row * 8 + w];
        float h[16];
        #pragma unroll
        for (int i = 0; i < 16; ++i) {
            int hk = q * 16 + i;
            const float4* wr = (const float4*)(W1 + (size_t)hk * 8);
            float4 A0 = __ldg(wr), A1 = __ldg(wr + 1);
            float hv = __ldg(b1 + hk);
            hv = fmaf(A0.x, ev[0], hv); hv = fmaf(A0.y, ev[1], hv);
            hv = fmaf(A0.z, ev[2], hv); hv = fmaf(A0.w, ev[3], hv);
            hv = fmaf(A1.x, ev[4], hv); hv = fmaf(A1.y, ev[5], hv);
            hv = fmaf(A1.z, ev[6], hv); hv = fmaf(A1.w, ev[7], hv);
            h[i] = fmaxf(hv, 0.0f);
        }
        // wait for all GEMM1 As0 reads before overwrite
        __syncthreads();
        uint2* dst = As2 + row * BST + (q * 2) * 4;
        #pragma unroll
        for (int u = 0; u < 4; ++u) {
            dst[u]     = make_uint2(f2tf32(h[u]),     f2tf32(h[u + 4]));
            dst[4 + u] = make_uint2(f2tf32(h[8 + u]), f2tf32(h[12 + u]));
        }
    }
    __syncthreads();

    // ---------------- Phase 4: GEMM2 out = H @ W2^T + b2 (proven code) -------
    {
        int wm2 = (wid >> 2) * 32;
        int wn2 = (wid & 3) * 32;
        #pragma unroll
        for (int it = 0; it < 4; ++it) {
            int bn = it * 128;
            const float4* Wg = (const float4*)(W2 + (size_t)bn * 64);
            #pragma unroll
            for (int i = 0; i < 4; ++i) {
                int task = i * 256 + t;
                int rowN = task >> 3, kk = task & 7;
                float4 b0 = __ldg(Wg + rowN * 16 + kk * 2);
                float4 b1v = __ldg(Wg + rowN * 16 + kk * 2 + 1);
                uint2* pb = Bsl + rowN * BST + kk * 4;
                pb[0] = make_uint2(f2tf32(b0.x), f2tf32(b1v.x));
                pb[1] = make_uint2(f2tf32(b0.y), f2tf32(b1v.y));
                pb[2] = make_uint2(f2tf32(b0.z), f2tf32(b1v.z));
                pb[3] = make_uint2(f2tf32(b0.w), f2tf32(b1v.w));
            }
            __syncthreads();

            float acc[2][4][4];
            #pragma unroll
            for (int f = 0; f < 2; ++f)
                #pragma unroll
                for (int j = 0; j < 4; ++j)
                    #pragma unroll
                    for (int q = 0; q < 4; ++q) acc[f][j][q] = 0.0f;

            #pragma unroll
            for (int kk = 0; kk < 8; ++kk) {
                int kb = kk * 4 + tg;
                uint2 va0 = As2[(wm2 + g) * BST + kb];
                uint2 va1 = As2[(wm2 + g + 8) * BST + kb];
                uint2 va2 = As2[(wm2 + g + 16) * BST + kb];
                uint2 va3 = As2[(wm2 + g + 24) * BST + kb];
                uint32_t a[2][4] = {
                    { va0.x, va1.x, va0.y, va1.y },
                    { va2.x, va3.x, va2.y, va3.y }
                };
                uint2 wb[4];
                #pragma unroll
                for (int j = 0; j < 4; ++j)
                    wb[j] = Bsl[(wn2 + j * 8 + g) * BST + kb];

                #pragma unroll
                for (int f = 0; f < 2; ++f)
                    #pragma unroll
                    for (int j = 0; j < 4; ++j)
                        asm volatile(
                            "mma.sync.aligned.m16n8k8.row.col.f32.tf32.tf32.f32 "
                            "{%0,%1,%2,%3}, {%4,%5,%6,%7}, {%8,%9}, {%0,%1,%2,%3};"
                            : "+f"(acc[f][j][0]), "+f"(acc[f][j][1]),
                              "+f"(acc[f][j][2]), "+f"(acc[f][j][3])
                            : "r"(a[f][0]), "r"(a[f][1]), "r"(a[f][2]), "r"(a[f][3]),
                              "r"(wb[j].x), "r"(wb[j].y));
            }

            #pragma unroll
            for (int j = 0; j < 4; ++j) {
                int col = bn + wn2 + j * 8 + tg * 2;
                float2 bias = __ldg((const float2*)(b2 + col));
                #pragma unroll
                for (int f = 0; f < 2; ++f) {
                    int row = bm + wm2 + f * 16 + g;
                    float2 o0 = { acc[f][j][0] + bias.x, acc[f][j][1] + bias.y };
                    float2 o1 = { acc[f][j][2] + bias.x, acc[f][j][3] + bias.y };
                    *(float2*)(out + (size_t)row * 512 + col)       = o0;
                    *(float2*)(out + (size_t)(row + 8) * 512 + col) = o1;
                }
            }
            __syncthreads();
        }
    }
}

// ============================================================================
// Launch
// ============================================================================
extern "C" void kernel_launch(void* const* d_in, const int* in_sizes, int n_in,
                              void* d_out, int out_size) {
    const float* x   = (const float*)d_in[0];
    const float* ryt = (const float*)d_in[1];
    const float* rp  = (const float*)d_in[2];
    const float* W1  = (const float*)d_in[3];
    const float* b1  = (const float*)d_in[4];
    const float* W2  = (const float*)d_in[5];
    const float* b2  = (const float*)d_in[6];
    float* out = (float*)d_out;

    int rows = in_sizes[0] / 512;            // B*S = 16384

    build_u_kernel<<<32, 256>>>(rp, ryt);

    const int smem = (64 * AST + 4608) * (int)sizeof(uint2)   // As0 + Bsl
                   + (4 * 64 * 8 + 64 * 8) * (int)sizeof(float); // evb + evf
    cudaFuncSetAttribute(qff_kernel, cudaFuncAttributeMaxDynamicSharedMemorySize, smem);
    qff_kernel<<<rows / 64, 256, smem>>>(x, W1, b1, W2, b2, out);
}